// round 1
// baseline (speedup 1.0000x reference)
#include <cuda_runtime.h>
#include <math.h>

#define NB   2
#define CIN  256
#define HH   96
#define WW   96
#define HW   9216
#define BC   128
#define C4   512     // 4*BC
#define C5   640     // 5*BC
#define COUT 256
#define POOLP 10

// Scratch (static __device__ allowed; no cudaMalloc)
__device__ float g_tmp [NB * C5 * HW];   // conv1 out -> normalized (ch<512 feat4 NCHW, ch>=512 fm_short)
__device__ float g_cl  [NB * HW * C4];   // feat4 channels-last for border_align
__device__ float g_ltrb[NB * C4 * HW];   // border-aligned, reshaped to NCHW per reference reshape
__device__ float g_am  [NB * C5 * HW];   // align * mask
__device__ float g_mean[NB * C5];
__device__ float g_rstd[NB * C5];

// ---------------------------------------------------------------------------
// Kernel 1: combined 1x1 conv GEMM:  g_tmp[n][m][p] = sum_k Wrow(m)[k]*feat[n][k][p]
// m<512 -> w_ltrb, m>=512 -> w_cur. Biases skipped (cancel exactly in InstanceNorm).
// ---------------------------------------------------------------------------
__global__ __launch_bounds__(256) void k_gemm1(const float* __restrict__ feat,
                                               const float* __restrict__ w_ltrb,
                                               const float* __restrict__ w_cur) {
    const int p0 = blockIdx.x * 64;
    const int m0 = blockIdx.y * 64;
    const int n  = blockIdx.z;
    __shared__ float Ws[16][64];
    __shared__ float Xs[16][64];
    const int tid = threadIdx.x;
    const int tm = tid >> 4, tn = tid & 15;
    float acc[4][4] = {};
    const float* X = feat + (size_t)n * CIN * HW;

    for (int k0 = 0; k0 < CIN; k0 += 16) {
#pragma unroll
        for (int it = 0; it < 4; it++) {
            int e = tid + it * 256;
            int k = e >> 6, m = e & 63;
            int gm = m0 + m;
            Ws[k][m] = (gm < C4) ? w_ltrb[gm * CIN + k0 + k]
                                 : w_cur[(gm - C4) * CIN + k0 + k];
        }
#pragma unroll
        for (int it = 0; it < 4; it++) {
            int e = tid + it * 256;
            int k = e >> 6, p = e & 63;
            Xs[k][p] = X[(k0 + k) * HW + p0 + p];
        }
        __syncthreads();
#pragma unroll
        for (int k = 0; k < 16; k++) {
            const float4 wv = *(const float4*)(&Ws[k][tm * 4]);
            const float4 xv = *(const float4*)(&Xs[k][tn * 4]);
            float wr[4] = {wv.x, wv.y, wv.z, wv.w};
            float xr[4] = {xv.x, xv.y, xv.z, xv.w};
#pragma unroll
            for (int i = 0; i < 4; i++)
#pragma unroll
                for (int j = 0; j < 4; j++) acc[i][j] += wr[i] * xr[j];
        }
        __syncthreads();
    }
#pragma unroll
    for (int i = 0; i < 4; i++)
#pragma unroll
        for (int j = 0; j < 4; j++)
            g_tmp[((size_t)n * C5 + m0 + tm * 4 + i) * HW + p0 + tn * 4 + j] = acc[i][j];
}

// ---------------------------------------------------------------------------
// Kernel 2: per-(n,c) instance-norm stats over HW
// ---------------------------------------------------------------------------
__global__ __launch_bounds__(256) void k_stats() {
    const int nc = blockIdx.x;
    const float* x = g_tmp + (size_t)nc * HW;
    float s = 0.f, ss = 0.f;
    for (int i = threadIdx.x; i < HW; i += 256) { float v = x[i]; s += v; ss += v * v; }
    __shared__ float sh1[256], sh2[256];
    sh1[threadIdx.x] = s; sh2[threadIdx.x] = ss;
    __syncthreads();
    for (int st = 128; st > 0; st >>= 1) {
        if (threadIdx.x < st) {
            sh1[threadIdx.x] += sh1[threadIdx.x + st];
            sh2[threadIdx.x] += sh2[threadIdx.x + st];
        }
        __syncthreads();
    }
    if (threadIdx.x == 0) {
        float m = sh1[0] * (1.f / HW);
        float var = sh2[0] * (1.f / HW) - m * m;
        g_mean[nc] = m;
        g_rstd[nc] = rsqrtf(var + 1e-5f);
    }
}

// ---------------------------------------------------------------------------
// Kernel 3: normalize + relu in place
// ---------------------------------------------------------------------------
__global__ __launch_bounds__(256) void k_norm() {
    int idx = blockIdx.x * 256 + threadIdx.x;
    int nc = idx / HW;
    float v = (g_tmp[idx] - g_mean[nc]) * g_rstd[nc];
    g_tmp[idx] = fmaxf(v, 0.f);
}

// ---------------------------------------------------------------------------
// Kernel 4: transpose feat4 (channels 0..511 of g_tmp) NCHW -> channels-last
// ---------------------------------------------------------------------------
__global__ void k_transpose() {
    __shared__ float tile[32][33];
    const int n  = blockIdx.z;
    const int c0 = blockIdx.y * 32;
    const int p0 = blockIdx.x * 32;
    const int tx = threadIdx.x;   // 32
    const int ty = threadIdx.y;   // 8
#pragma unroll
    for (int i = 0; i < 32; i += 8)
        tile[ty + i][tx] = g_tmp[((size_t)n * C5 + c0 + ty + i) * HW + p0 + tx];
    __syncthreads();
#pragma unroll
    for (int i = 0; i < 32; i += 8)
        g_cl[((size_t)n * HW + p0 + ty + i) * C4 + c0 + tx] = tile[tx][ty + i];
}

// ---------------------------------------------------------------------------
// Kernel 5: border_align. One warp per (n, hw, border). Lane handles 4
// channels via one float4 per bilinear neighbor (channels-last layout).
// Output scattered per the reference transpose+reshape mapping.
// ---------------------------------------------------------------------------
__global__ __launch_bounds__(256) void k_border(const float* __restrict__ boxes) {
    const int unit = (blockIdx.x * 256 + threadIdx.x) >> 5;
    const int lane = threadIdx.x & 31;
    if (unit >= NB * HW * 4) return;
    const int n   = unit / (HW * 4);
    const int rem = unit - n * (HW * 4);
    const int hw  = rem >> 2;
    const int b   = rem & 3;

    const float* bx = boxes + ((size_t)n * HW + hw) * 4;
    const float x1 = bx[0], y1 = bx[1], x2 = bx[2], y2 = bx[3];
    const float bw = (x2 - x1) * (1.f / POOLP);
    const float bh = (y2 - y1) * (1.f / POOLP);
    float sx, sy, dx, dy;
    if (b == 0)      { sx = x1; sy = y1; dx = bw;  dy = 0.f; }
    else if (b == 1) { sx = x1; sy = y1; dx = 0.f; dy = bh;  }
    else if (b == 2) { sx = x1; sy = y2; dx = bw;  dy = 0.f; }
    else             { sx = x2; sy = y1; dx = 0.f; dy = bh;  }

    const float* base = g_cl + (size_t)n * HW * C4 + b * BC + lane * 4;

    float4 acc = make_float4(-INFINITY, -INFINITY, -INFINITY, -INFINITY);
#pragma unroll
    for (int i = 0; i <= POOLP; i++) {
        float x = sx + dx * (float)i;
        float y = sy + dy * (float)i;
        bool valid = (x >= -1.f) && (x <= (float)WW) && (y >= -1.f) && (y <= (float)HH);
        float xc = fminf(fmaxf(x, 0.f), (float)(WW - 1));
        float yc = fminf(fmaxf(y, 0.f), (float)(HH - 1));
        int x0 = (int)floorf(xc); if (x0 > WW - 1) x0 = WW - 1;
        int y0 = (int)floorf(yc); if (y0 > HH - 1) y0 = HH - 1;
        int x1i = min(x0 + 1, WW - 1);
        int y1i = min(y0 + 1, HH - 1);
        float lx = (x0 >= WW - 1) ? 0.f : xc - (float)x0;
        float ly = (y0 >= HH - 1) ? 0.f : yc - (float)y0;
        float hx = 1.f - lx, hy = 1.f - ly;
        float w00 = hy * hx, w01 = hy * lx, w10 = ly * hx, w11 = ly * lx;

        const float4 v00 = *(const float4*)(base + (size_t)(y0 * WW + x0) * C4);
        const float4 v01 = *(const float4*)(base + (size_t)(y0 * WW + x1i) * C4);
        const float4 v10 = *(const float4*)(base + (size_t)(y1i * WW + x0) * C4);
        const float4 v11 = *(const float4*)(base + (size_t)(y1i * WW + x1i) * C4);

        float4 val;
        val.x = valid ? (v00.x * w00 + v01.x * w01 + v10.x * w10 + v11.x * w11) : 0.f;
        val.y = valid ? (v00.y * w00 + v01.y * w01 + v10.y * w10 + v11.y * w11) : 0.f;
        val.z = valid ? (v00.z * w00 + v01.z * w01 + v10.z * w10 + v11.z * w11) : 0.f;
        val.w = valid ? (v00.w * w00 + v01.w * w01 + v10.w * w10 + v11.w * w11) : 0.f;
        acc.x = fmaxf(acc.x, val.x);
        acc.y = fmaxf(acc.y, val.y);
        acc.z = fmaxf(acc.z, val.z);
        acc.w = fmaxf(acc.w, val.w);
    }

    // reshape mapping: flat = bc*HW*4 + hw*4 + b -> ch = bc*4 + t/HW, pos = t%HW
    const int t   = hw * 4 + b;
    const int chq = t / HW;
    const int pos = t - chq * HW;
    const float v[4] = {acc.x, acc.y, acc.z, acc.w};
#pragma unroll
    for (int k = 0; k < 4; k++) {
        int bc = lane * 4 + k;
        g_ltrb[((size_t)n * C4 + bc * 4 + chq) * HW + pos] = v[k];
    }
}

// ---------------------------------------------------------------------------
// Kernel 6: 3x3 conv [512 -> 640] pad=1 + bias + sigmoid, fused multiply by
// align (ltrb for co<512, fm_short for co>=512). Block: 64 co x (8x16) pixels.
// Each thread: 8 co x 4 px accumulators.
// ---------------------------------------------------------------------------
__global__ __launch_bounds__(256) void k_mask(const float* __restrict__ w_mask,
                                              const float* __restrict__ b_mask) {
    const int n   = blockIdx.z;
    const int co0 = blockIdx.y * 64;
    const int tile = blockIdx.x;          // 12 row-tiles x 6 col-tiles
    const int gy0 = (tile / 6) * 8;
    const int gx0 = (tile % 6) * 16;
    const int tid = threadIdx.x;
    const int tc  = tid >> 5;             // 0..7 -> co block of 8
    const int tp  = tid & 31;
    const int r   = tp >> 2;              // 0..7
    const int c0  = (tp & 3) * 4;         // 0,4,8,12

    __shared__ float Xs[8][10][18];       // ci x (rows+2) x (cols+2)
    __shared__ float Ws[72][64];          // (ci*9+k) x co

    float acc[8][4] = {};
    const float* Xbase = g_tmp + (size_t)n * C5 * HW;

    for (int ci0 = 0; ci0 < C4; ci0 += 8) {
        for (int e = tid; e < 1440; e += 256) {
            int ci = e / 180;
            int rr = (e % 180) / 18;
            int cc = e % 18;
            int gy = gy0 + rr - 1;
            int gx = gx0 + cc - 1;
            float vv = 0.f;
            if ((unsigned)gy < (unsigned)HH && (unsigned)gx < (unsigned)WW)
                vv = Xbase[(size_t)(ci0 + ci) * HW + gy * WW + gx];
            Xs[ci][rr][cc] = vv;
        }
#pragma unroll
        for (int it = 0; it < 18; it++) {
            int e = tid + it * 256;
            int s = e >> 6;               // 0..71
            int co = e & 63;
            int ci = s / 9, k = s - ci * 9;
            Ws[s][co] = w_mask[((size_t)(co0 + co) * C4 + ci0 + ci) * 9 + k];
        }
        __syncthreads();
#pragma unroll
        for (int ci = 0; ci < 8; ci++)
#pragma unroll
            for (int ky = 0; ky < 3; ky++)
#pragma unroll
                for (int kx = 0; kx < 3; kx++) {
                    float iv[4];
#pragma unroll
                    for (int j = 0; j < 4; j++) iv[j] = Xs[ci][r + ky][c0 + kx + j];
                    const int s = ci * 9 + ky * 3 + kx;
                    const float4 wa = *(const float4*)(&Ws[s][tc * 8]);
                    const float4 wb = *(const float4*)(&Ws[s][tc * 8 + 4]);
                    const float wr[8] = {wa.x, wa.y, wa.z, wa.w, wb.x, wb.y, wb.z, wb.w};
#pragma unroll
                    for (int i = 0; i < 8; i++)
#pragma unroll
                        for (int j = 0; j < 4; j++) acc[i][j] += wr[i] * iv[j];
                }
        __syncthreads();
    }
#pragma unroll
    for (int i = 0; i < 8; i++) {
        const int co = co0 + tc * 8 + i;
        const float bias = b_mask[co];
#pragma unroll
        for (int j = 0; j < 4; j++) {
            const int p = (gy0 + r) * WW + gx0 + c0 + j;
            const float m = 1.f / (1.f + __expf(-(acc[i][j] + bias)));
            const float a = (co < C4) ? g_ltrb[((size_t)n * C4 + co) * HW + p]
                                      : g_tmp[((size_t)n * C5 + co) * HW + p];
            g_am[((size_t)n * C5 + co) * HW + p] = m * a;
        }
    }
}

// ---------------------------------------------------------------------------
// Kernel 7: final 1x1 conv [640 -> 256] + bias + relu -> d_out
// ---------------------------------------------------------------------------
__global__ __launch_bounds__(256) void k_gemm2(const float* __restrict__ w_border,
                                               const float* __restrict__ b_border,
                                               float* __restrict__ out) {
    const int p0 = blockIdx.x * 64;
    const int m0 = blockIdx.y * 64;
    const int n  = blockIdx.z;
    __shared__ float Ws[16][64];
    __shared__ float Xs[16][64];
    const int tid = threadIdx.x;
    const int tm = tid >> 4, tn = tid & 15;
    float acc[4][4] = {};
    const float* X = g_am + (size_t)n * C5 * HW;

    for (int k0 = 0; k0 < C5; k0 += 16) {
#pragma unroll
        for (int it = 0; it < 4; it++) {
            int e = tid + it * 256;
            int k = e >> 6, m = e & 63;
            Ws[k][m] = w_border[(m0 + m) * C5 + k0 + k];
        }
#pragma unroll
        for (int it = 0; it < 4; it++) {
            int e = tid + it * 256;
            int k = e >> 6, p = e & 63;
            Xs[k][p] = X[(k0 + k) * HW + p0 + p];
        }
        __syncthreads();
#pragma unroll
        for (int k = 0; k < 16; k++) {
            const float4 wv = *(const float4*)(&Ws[k][tm * 4]);
            const float4 xv = *(const float4*)(&Xs[k][tn * 4]);
            float wr[4] = {wv.x, wv.y, wv.z, wv.w};
            float xr[4] = {xv.x, xv.y, xv.z, xv.w};
#pragma unroll
            for (int i = 0; i < 4; i++)
#pragma unroll
                for (int j = 0; j < 4; j++) acc[i][j] += wr[i] * xr[j];
        }
        __syncthreads();
    }
#pragma unroll
    for (int i = 0; i < 4; i++) {
        const float bias = b_border[m0 + tm * 4 + i];
#pragma unroll
        for (int j = 0; j < 4; j++)
            out[((size_t)n * COUT + m0 + tm * 4 + i) * HW + p0 + tn * 4 + j] =
                fmaxf(acc[i][j] + bias, 0.f);
    }
}

// ---------------------------------------------------------------------------
extern "C" void kernel_launch(void* const* d_in, const int* in_sizes, int n_in,
                              void* d_out, int out_size) {
    const float* feature  = (const float*)d_in[0];
    const float* boxes    = (const float*)d_in[1];
    // d_in[2] = wh (unused by forward)
    // d_in[4] = b_cur, d_in[6] = b_ltrb : cancel exactly inside InstanceNorm -> skipped
    const float* w_cur    = (const float*)d_in[3];
    const float* w_ltrb   = (const float*)d_in[5];
    const float* w_mask   = (const float*)d_in[7];
    const float* b_mask   = (const float*)d_in[8];
    const float* w_border = (const float*)d_in[9];
    const float* b_border = (const float*)d_in[10];
    float* out = (float*)d_out;

    k_gemm1<<<dim3(HW / 64, C5 / 64, NB), 256>>>(feature, w_ltrb, w_cur);
    k_stats<<<NB * C5, 256>>>();
    k_norm<<<(NB * C5 * HW) / 256, 256>>>();
    k_transpose<<<dim3(HW / 32, C4 / 32, NB), dim3(32, 8)>>>();
    k_border<<<(NB * HW * 4) / 8, 256>>>(boxes);
    k_mask<<<dim3(72, C5 / 64, NB), 256>>>(w_mask, b_mask);
    k_gemm2<<<dim3(HW / 64, COUT / 64, NB), 256>>>(w_border, b_border, out);
}

// round 4
// speedup vs baseline: 2.3148x; 2.3148x over previous
#include <cuda_runtime.h>
#include <cuda_bf16.h>
#include <math.h>
#include <stdint.h>

#define NB   2
#define CIN  256
#define HH   96
#define WW   96
#define HW   9216
#define BC   128
#define C4   512     // 4*BC
#define C5   640     // 5*BC
#define COUT 256
#define POOLP 10

// Padded position space for the 3x3 conv GEMM
#define PW    98          // 96+2
#define NPOS  9604        // 98*98
#define BLK_N 128         // pos per block
#define BLK_M 128         // co per block
#define NPTIL 76          // ceil(9604/128)
#define POSPAD (NPTIL*BLK_N)   // 9728
#define GUARD 128
#define BROWS (GUARD + POSPAD + GUARD)  // 9984
#define KEFF  1536        // [hi(512) | lo(512) | hi(512)]
#define KC    64          // bf16 per K-chunk (=128B row)
#define NCHUNK (KEFF/KC)  // 24
#define NTAPS 9
#define CHUNKS (NTAPS*NCHUNK)  // 216
#define STAGES 3
#define A_BYTES (BLK_M*KC*2)   // 16384
#define B_BYTES (BLK_N*KC*2)   // 16384
#define STAGE_BYTES (A_BYTES + B_BYTES)  // 32768
#define DYN_SMEM (STAGES*STAGE_BYTES)    // 98304

// Scratch
__device__ float g_tmp [NB * C5 * HW];
__device__ float g_cl  [NB * HW * C4];
__device__ float g_ltrb[NB * C4 * HW];
__device__ float g_am  [NB * C5 * HW];
__device__ float g_mean[NB * C5];
__device__ float g_rstd[NB * C5];
__device__ __nv_bfloat16 g_bbuf[(size_t)NB * BROWS * KEFF];   // padded channels-last acts
__device__ __nv_bfloat16 g_abuf[(size_t)NTAPS * C5 * KEFF];   // weights per tap

#define SW128(off) ((off) ^ (((off) >> 3) & 0x70))

// ---------------------------------------------------------------------------
// PTX helpers (sm_80-compatible only: cp.async / ldmatrix / mma.sync)
// ---------------------------------------------------------------------------
__device__ __forceinline__ uint32_t smem_u32(const void* p) {
    uint32_t a;
    asm("{ .reg .u64 t; cvta.to.shared.u64 t, %1; cvt.u32.u64 %0, t; }"
        : "=r"(a) : "l"(p));
    return a;
}
__device__ __forceinline__ void cpasync16(uint32_t dst, const void* src) {
    asm volatile("cp.async.cg.shared.global [%0], [%1], 16;" :: "r"(dst), "l"(src));
}
__device__ __forceinline__ void cp_commit() {
    asm volatile("cp.async.commit_group;" ::: "memory");
}
template <int N>
__device__ __forceinline__ void cp_wait() {
    asm volatile("cp.async.wait_group %0;" :: "n"(N) : "memory");
}
__device__ __forceinline__ void ldsm_x4(uint32_t& r0, uint32_t& r1, uint32_t& r2,
                                        uint32_t& r3, uint32_t addr) {
    asm volatile("ldmatrix.sync.aligned.m8n8.x4.shared.b16 {%0,%1,%2,%3}, [%4];"
                 : "=r"(r0), "=r"(r1), "=r"(r2), "=r"(r3) : "r"(addr));
}
__device__ __forceinline__ void ldsm_x2(uint32_t& r0, uint32_t& r1, uint32_t addr) {
    asm volatile("ldmatrix.sync.aligned.m8n8.x2.shared.b16 {%0,%1}, [%2];"
                 : "=r"(r0), "=r"(r1) : "r"(addr));
}
__device__ __forceinline__ void mma16816(float* c, uint32_t a0, uint32_t a1,
                                         uint32_t a2, uint32_t a3,
                                         uint32_t b0, uint32_t b1) {
    asm volatile(
        "mma.sync.aligned.m16n8k16.row.col.f32.bf16.bf16.f32 "
        "{%0,%1,%2,%3}, {%4,%5,%6,%7}, {%8,%9}, {%0,%1,%2,%3};"
        : "+f"(c[0]), "+f"(c[1]), "+f"(c[2]), "+f"(c[3])
        : "r"(a0), "r"(a1), "r"(a2), "r"(a3), "r"(b0), "r"(b1));
}

// ---------------------------------------------------------------------------
// Kernel 1: combined 1x1 conv GEMM (biases cancel in InstanceNorm)
// ---------------------------------------------------------------------------
__global__ __launch_bounds__(256) void k_gemm1(const float* __restrict__ feat,
                                               const float* __restrict__ w_ltrb,
                                               const float* __restrict__ w_cur) {
    const int p0 = blockIdx.x * 64;
    const int m0 = blockIdx.y * 64;
    const int n  = blockIdx.z;
    __shared__ float Ws[16][64];
    __shared__ float Xs[16][64];
    const int tid = threadIdx.x;
    const int tm = tid >> 4, tn = tid & 15;
    float acc[4][4] = {};
    const float* X = feat + (size_t)n * CIN * HW;

    for (int k0 = 0; k0 < CIN; k0 += 16) {
#pragma unroll
        for (int it = 0; it < 4; it++) {
            int e = tid + it * 256;
            int k = e >> 6, m = e & 63;
            int gm = m0 + m;
            Ws[k][m] = (gm < C4) ? w_ltrb[gm * CIN + k0 + k]
                                 : w_cur[(gm - C4) * CIN + k0 + k];
        }
#pragma unroll
        for (int it = 0; it < 4; it++) {
            int e = tid + it * 256;
            int k = e >> 6, p = e & 63;
            Xs[k][p] = X[(k0 + k) * HW + p0 + p];
        }
        __syncthreads();
#pragma unroll
        for (int k = 0; k < 16; k++) {
            const float4 wv = *(const float4*)(&Ws[k][tm * 4]);
            const float4 xv = *(const float4*)(&Xs[k][tn * 4]);
            float wr[4] = {wv.x, wv.y, wv.z, wv.w};
            float xr[4] = {xv.x, xv.y, xv.z, xv.w};
#pragma unroll
            for (int i = 0; i < 4; i++)
#pragma unroll
                for (int j = 0; j < 4; j++) acc[i][j] += wr[i] * xr[j];
        }
        __syncthreads();
    }
#pragma unroll
    for (int i = 0; i < 4; i++)
#pragma unroll
        for (int j = 0; j < 4; j++)
            g_tmp[((size_t)n * C5 + m0 + tm * 4 + i) * HW + p0 + tn * 4 + j] = acc[i][j];
}

// ---------------------------------------------------------------------------
// Kernel 2: instance-norm stats
// ---------------------------------------------------------------------------
__global__ __launch_bounds__(256) void k_stats() {
    const int nc = blockIdx.x;
    const float* x = g_tmp + (size_t)nc * HW;
    float s = 0.f, ss = 0.f;
    for (int i = threadIdx.x; i < HW; i += 256) { float v = x[i]; s += v; ss += v * v; }
    __shared__ float sh1[256], sh2[256];
    sh1[threadIdx.x] = s; sh2[threadIdx.x] = ss;
    __syncthreads();
    for (int st = 128; st > 0; st >>= 1) {
        if (threadIdx.x < st) {
            sh1[threadIdx.x] += sh1[threadIdx.x + st];
            sh2[threadIdx.x] += sh2[threadIdx.x + st];
        }
        __syncthreads();
    }
    if (threadIdx.x == 0) {
        float m = sh1[0] * (1.f / HW);
        float var = sh2[0] * (1.f / HW) - m * m;
        g_mean[nc] = m;
        g_rstd[nc] = rsqrtf(var + 1e-5f);
    }
}

// ---------------------------------------------------------------------------
// Kernel 3: normalize + relu in place
// ---------------------------------------------------------------------------
__global__ __launch_bounds__(256) void k_norm() {
    int idx = blockIdx.x * 256 + threadIdx.x;
    int nc = idx / HW;
    float v = (g_tmp[idx] - g_mean[nc]) * g_rstd[nc];
    g_tmp[idx] = fmaxf(v, 0.f);
}

// ---------------------------------------------------------------------------
// Kernel 3b: zero the padded bf16 activation buffer
// ---------------------------------------------------------------------------
__global__ __launch_bounds__(256) void k_zero_b() {
    size_t i = (size_t)blockIdx.x * 256 + threadIdx.x;
    size_t total = ((size_t)NB * BROWS * KEFF) / 8;
    if (i < total) ((uint4*)g_bbuf)[i] = make_uint4(0, 0, 0, 0);
}

// ---------------------------------------------------------------------------
// Kernel 4: transpose feat4 NCHW -> channels-last fp32 (border_align) AND
// build padded channels-last bf16 [hi|lo|hi] buffer for the tensor-core conv.
// ---------------------------------------------------------------------------
__global__ void k_transpose() {
    __shared__ float tile[32][33];
    const int n  = blockIdx.z;
    const int c0 = blockIdx.y * 32;
    const int p0 = blockIdx.x * 32;
    const int tx = threadIdx.x;
    const int ty = threadIdx.y;
#pragma unroll
    for (int i = 0; i < 32; i += 8)
        tile[ty + i][tx] = g_tmp[((size_t)n * C5 + c0 + ty + i) * HW + p0 + tx];
    __syncthreads();
#pragma unroll
    for (int i = 0; i < 32; i += 8) {
        const int p = p0 + ty + i;
        const float v = tile[tx][ty + i];
        g_cl[((size_t)n * HW + p) * C4 + c0 + tx] = v;
        const int y = p / WW, x = p - y * WW;
        const int row = GUARD + (y + 1) * PW + (x + 1);
        __nv_bfloat16 hi = __float2bfloat16(v);
        __nv_bfloat16 lo = __float2bfloat16(v - __bfloat162float(hi));
        const size_t base = ((size_t)n * BROWS + row) * KEFF + c0 + tx;
        g_bbuf[base]        = hi;
        g_bbuf[base + 512]  = lo;
        g_bbuf[base + 1024] = hi;
    }
}

// ---------------------------------------------------------------------------
// Kernel 4b: weight prep -> g_abuf[tap][co][ hi(ci) | hi(ci) | lo(ci) ]
// ---------------------------------------------------------------------------
__global__ __launch_bounds__(256) void k_wprep(const float* __restrict__ w_mask) {
    int idx = blockIdx.x * 256 + threadIdx.x;
    if (idx >= NTAPS * C5 * C4) return;
    const int ci  = idx & (C4 - 1);
    const int co  = (idx >> 9) % C5;
    const int tap = idx / (C4 * C5);
    const float w = w_mask[((size_t)co * C4 + ci) * 9 + tap];
    __nv_bfloat16 hi = __float2bfloat16(w);
    __nv_bfloat16 lo = __float2bfloat16(w - __bfloat162float(hi));
    const size_t base = ((size_t)tap * C5 + co) * KEFF + ci;
    g_abuf[base]        = hi;
    g_abuf[base + 512]  = hi;
    g_abuf[base + 1024] = lo;
}

// ---------------------------------------------------------------------------
// Kernel 5: border_align
// ---------------------------------------------------------------------------
__global__ __launch_bounds__(256) void k_border(const float* __restrict__ boxes) {
    const int unit = (blockIdx.x * 256 + threadIdx.x) >> 5;
    const int lane = threadIdx.x & 31;
    if (unit >= NB * HW * 4) return;
    const int n   = unit / (HW * 4);
    const int rem = unit - n * (HW * 4);
    const int hw  = rem >> 2;
    const int b   = rem & 3;

    const float* bx = boxes + ((size_t)n * HW + hw) * 4;
    const float x1 = bx[0], y1 = bx[1], x2 = bx[2], y2 = bx[3];
    const float bw = (x2 - x1) * (1.f / POOLP);
    const float bh = (y2 - y1) * (1.f / POOLP);
    float sx, sy, dx, dy;
    if (b == 0)      { sx = x1; sy = y1; dx = bw;  dy = 0.f; }
    else if (b == 1) { sx = x1; sy = y1; dx = 0.f; dy = bh;  }
    else if (b == 2) { sx = x1; sy = y2; dx = bw;  dy = 0.f; }
    else             { sx = x2; sy = y1; dx = 0.f; dy = bh;  }

    const float* base = g_cl + (size_t)n * HW * C4 + b * BC + lane * 4;

    float4 acc = make_float4(-INFINITY, -INFINITY, -INFINITY, -INFINITY);
#pragma unroll
    for (int i = 0; i <= POOLP; i++) {
        float x = sx + dx * (float)i;
        float y = sy + dy * (float)i;
        bool valid = (x >= -1.f) && (x <= (float)WW) && (y >= -1.f) && (y <= (float)HH);
        float xc = fminf(fmaxf(x, 0.f), (float)(WW - 1));
        float yc = fminf(fmaxf(y, 0.f), (float)(HH - 1));
        int x0 = (int)floorf(xc); if (x0 > WW - 1) x0 = WW - 1;
        int y0 = (int)floorf(yc); if (y0 > HH - 1) y0 = HH - 1;
        int x1i = min(x0 + 1, WW - 1);
        int y1i = min(y0 + 1, HH - 1);
        float lx = (x0 >= WW - 1) ? 0.f : xc - (float)x0;
        float ly = (y0 >= HH - 1) ? 0.f : yc - (float)y0;
        float hx = 1.f - lx, hy = 1.f - ly;
        float w00 = hy * hx, w01 = hy * lx, w10 = ly * hx, w11 = ly * lx;

        const float4 v00 = *(const float4*)(base + (size_t)(y0 * WW + x0) * C4);
        const float4 v01 = *(const float4*)(base + (size_t)(y0 * WW + x1i) * C4);
        const float4 v10 = *(const float4*)(base + (size_t)(y1i * WW + x0) * C4);
        const float4 v11 = *(const float4*)(base + (size_t)(y1i * WW + x1i) * C4);

        float4 val;
        val.x = valid ? (v00.x * w00 + v01.x * w01 + v10.x * w10 + v11.x * w11) : 0.f;
        val.y = valid ? (v00.y * w00 + v01.y * w01 + v10.y * w10 + v11.y * w11) : 0.f;
        val.z = valid ? (v00.z * w00 + v01.z * w01 + v10.z * w10 + v11.z * w11) : 0.f;
        val.w = valid ? (v00.w * w00 + v01.w * w01 + v10.w * w10 + v11.w * w11) : 0.f;
        acc.x = fmaxf(acc.x, val.x);
        acc.y = fmaxf(acc.y, val.y);
        acc.z = fmaxf(acc.z, val.z);
        acc.w = fmaxf(acc.w, val.w);
    }

    const int t   = hw * 4 + b;
    const int chq = t / HW;
    const int pos = t - chq * HW;
    const float v[4] = {acc.x, acc.y, acc.z, acc.w};
#pragma unroll
    for (int k = 0; k < 4; k++) {
        int bc = lane * 4 + k;
        g_ltrb[((size_t)n * C4 + bc * 4 + chq) * HW + pos] = v[k];
    }
}

// ---------------------------------------------------------------------------
// Kernel 6: mma.sync bf16 3x3 conv [512->640] + bias + sigmoid + align-mult.
// Block: 128 co x 128 pos. 8 warps, each 64co x 32pos. 3-stage cp.async pipe.
// ---------------------------------------------------------------------------
__device__ __forceinline__ void load_stage(uint32_t stage_base, const char* Ag,
                                           const char* Bg, int tid) {
#pragma unroll
    for (int it = 0; it < 8; it++) {
        const int v = tid + it * 256;
        const int row = (v >> 3) & 127;
        const int c16 = v & 7;
        const uint32_t off = SW128((uint32_t)(row * 128 + c16 * 16));
        if (v < 1024)
            cpasync16(stage_base + off, Ag + (size_t)row * (KEFF * 2) + c16 * 16);
        else
            cpasync16(stage_base + A_BYTES + off, Bg + (size_t)row * (KEFF * 2) + c16 * 16);
    }
}

__global__ __launch_bounds__(256) void k_mask_mma(const float* __restrict__ b_mask,
                                                  const float* __restrict__ /*unused*/) {
    extern __shared__ char smem[];
    const uint32_t sb = smem_u32(smem);
    const int tid  = threadIdx.x;
    const int wid  = tid >> 5;
    const int lane = tid & 31;
    const int n    = blockIdx.z;
    const int co0  = blockIdx.y * BLK_M;
    const int pos0 = blockIdx.x * BLK_N;
    const int wm   = wid & 1;          // co half (64)
    const int wn   = wid >> 1;         // pos quarter (32)

    const __nv_bfloat16* Bbase = g_bbuf + (size_t)n * BROWS * KEFF;

    // chunk c -> source pointers
    auto chunk_A = [&](int c) -> const char* {
        const int tap = c / NCHUNK;
        const int kb  = (c % NCHUNK) * KC;
        return (const char*)(g_abuf + ((size_t)tap * C5 + co0) * KEFF + kb);
    };
    auto chunk_B = [&](int c) -> const char* {
        const int tap  = c / NCHUNK;
        const int kb   = (c % NCHUNK) * KC;
        const int dtap = (tap / 3) * PW + (tap % 3) - (PW + 1);
        return (const char*)(Bbase + (size_t)(GUARD + pos0 + dtap) * KEFF + kb);
    };

    float acc[4][4][4] = {};

    // prologue: stages 0,1
    load_stage(sb, chunk_A(0), chunk_B(0), tid);
    cp_commit();
    load_stage(sb + STAGE_BYTES, chunk_A(1), chunk_B(1), tid);
    cp_commit();

    for (int c = 0; c < CHUNKS; c++) {
        if (c + 2 < CHUNKS)
            load_stage(sb + ((c + 2) % STAGES) * STAGE_BYTES,
                       chunk_A(c + 2), chunk_B(c + 2), tid);
        cp_commit();
        cp_wait<2>();
        __syncthreads();

        const uint32_t As = sb + (c % STAGES) * STAGE_BYTES;
        const uint32_t Bs = As + A_BYTES;
#pragma unroll
        for (int ks = 0; ks < 4; ks++) {
            const int kbyte = ks * 32;
            uint32_t a[4][4];
#pragma unroll
            for (int mt = 0; mt < 4; mt++) {
                const int row = wm * 64 + mt * 16 + (lane & 15);
                const uint32_t off = SW128((uint32_t)(row * 128 + kbyte + (lane >> 4) * 16));
                ldsm_x4(a[mt][0], a[mt][1], a[mt][2], a[mt][3], As + off);
            }
            uint32_t b[4][2];
#pragma unroll
            for (int nt = 0; nt < 4; nt++) {
                const int row = wn * 32 + nt * 8 + (lane & 7);
                const uint32_t off = SW128((uint32_t)(row * 128 + kbyte + ((lane >> 3) & 1) * 16));
                ldsm_x2(b[nt][0], b[nt][1], Bs + off);
            }
#pragma unroll
            for (int mt = 0; mt < 4; mt++)
#pragma unroll
                for (int nt = 0; nt < 4; nt++)
                    mma16816(acc[mt][nt], a[mt][0], a[mt][1], a[mt][2], a[mt][3],
                             b[nt][0], b[nt][1]);
        }
        __syncthreads();
    }

    // Epilogue: fragments -> bias + sigmoid + align multiply -> g_am
    const int col_b = (lane & 3) * 2;
    const int row_b = lane >> 2;
#pragma unroll
    for (int mt = 0; mt < 4; mt++) {
        const int coA = co0 + wm * 64 + mt * 16 + row_b;
        const int coB = coA + 8;
        const float biasA = b_mask[coA];
        const float biasB = b_mask[coB];
#pragma unroll
        for (int nt = 0; nt < 4; nt++) {
#pragma unroll
            for (int e = 0; e < 4; e++) {
                const int co   = (e < 2) ? coA : coB;
                const float bs = (e < 2) ? biasA : biasB;
                const int pp   = pos0 + wn * 32 + nt * 8 + col_b + (e & 1);
                const int py = pp / PW, px = pp - py * PW;
                const int y = py - 1, x = px - 1;
                if ((unsigned)y < (unsigned)HH && (unsigned)x < (unsigned)WW) {
                    const float vv = acc[mt][nt][e] + bs;
                    const float m = 1.f / (1.f + __expf(-vv));
                    const int p = y * WW + x;
                    const float a = (co < C4)
                        ? g_ltrb[((size_t)n * C4 + co) * HW + p]
                        : g_tmp [((size_t)n * C5 + co) * HW + p];
                    g_am[((size_t)n * C5 + co) * HW + p] = m * a;
                }
            }
        }
    }
}

// ---------------------------------------------------------------------------
// Kernel 7: final 1x1 conv [640 -> 256] + bias + relu -> d_out
// ---------------------------------------------------------------------------
__global__ __launch_bounds__(256) void k_gemm2(const float* __restrict__ w_border,
                                               const float* __restrict__ b_border,
                                               float* __restrict__ out) {
    const int p0 = blockIdx.x * 64;
    const int m0 = blockIdx.y * 64;
    const int n  = blockIdx.z;
    __shared__ float Ws[16][64];
    __shared__ float Xs[16][64];
    const int tid = threadIdx.x;
    const int tm = tid >> 4, tn = tid & 15;
    float acc[4][4] = {};
    const float* X = g_am + (size_t)n * C5 * HW;

    for (int k0 = 0; k0 < C5; k0 += 16) {
#pragma unroll
        for (int it = 0; it < 4; it++) {
            int e = tid + it * 256;
            int k = e >> 6, m = e & 63;
            Ws[k][m] = w_border[(m0 + m) * C5 + k0 + k];
        }
#pragma unroll
        for (int it = 0; it < 4; it++) {
            int e = tid + it * 256;
            int k = e >> 6, p = e & 63;
            Xs[k][p] = X[(k0 + k) * HW + p0 + p];
        }
        __syncthreads();
#pragma unroll
        for (int k = 0; k < 16; k++) {
            const float4 wv = *(const float4*)(&Ws[k][tm * 4]);
            const float4 xv = *(const float4*)(&Xs[k][tn * 4]);
            float wr[4] = {wv.x, wv.y, wv.z, wv.w};
            float xr[4] = {xv.x, xv.y, xv.z, xv.w};
#pragma unroll
            for (int i = 0; i < 4; i++)
#pragma unroll
                for (int j = 0; j < 4; j++) acc[i][j] += wr[i] * xr[j];
        }
        __syncthreads();
    }
#pragma unroll
    for (int i = 0; i < 4; i++) {
        const float bias = b_border[m0 + tm * 4 + i];
#pragma unroll
        for (int j = 0; j < 4; j++)
            out[((size_t)n * COUT + m0 + tm * 4 + i) * HW + p0 + tn * 4 + j] =
                fmaxf(acc[i][j] + bias, 0.f);
    }
}

// ---------------------------------------------------------------------------
extern "C" void kernel_launch(void* const* d_in, const int* in_sizes, int n_in,
                              void* d_out, int out_size) {
    const float* feature  = (const float*)d_in[0];
    const float* boxes    = (const float*)d_in[1];
    const float* w_cur    = (const float*)d_in[3];
    const float* w_ltrb   = (const float*)d_in[5];
    const float* w_mask   = (const float*)d_in[7];
    const float* b_mask   = (const float*)d_in[8];
    const float* w_border = (const float*)d_in[9];
    const float* b_border = (const float*)d_in[10];
    float* out = (float*)d_out;

    cudaFuncSetAttribute(k_mask_mma, cudaFuncAttributeMaxDynamicSharedMemorySize,
                         DYN_SMEM);

    k_gemm1<<<dim3(HW / 64, C5 / 64, NB), 256>>>(feature, w_ltrb, w_cur);
    k_stats<<<NB * C5, 256>>>();
    k_norm<<<(NB * C5 * HW) / 256, 256>>>();
    {
        size_t total = ((size_t)NB * BROWS * KEFF) / 8;
        int blocks = (int)((total + 255) / 256);
        k_zero_b<<<blocks, 256>>>();
    }
    k_transpose<<<dim3(HW / 32, C4 / 32, NB), dim3(32, 8)>>>();
    {
        int tot = NTAPS * C5 * C4;
        k_wprep<<<(tot + 255) / 256, 256>>>(w_mask);
    }
    k_border<<<(NB * HW * 4) / 8, 256>>>(boxes);
    k_mask_mma<<<dim3(NPTIL, C5 / BLK_M, NB), 256, DYN_SMEM>>>(b_mask, nullptr);
    k_gemm2<<<dim3(HW / 64, COUT / 64, NB), 256>>>(w_border, b_border, out);
}